// round 14
// baseline (speedup 1.0000x reference)
#include <cuda_runtime.h>
#include <math.h>

#define N_INST 128
#define NV     128
#define IMG    512
#define RES    64
#define SPLIT  16                   // 16 blocks per instance, 4 rows each
#define THREADS 128
#define PPT     2                   // 2 consecutive x per thread (one row)
#define NPAIR   (PPT/2)             // 1
#define NBLOCKS (N_INST*SPLIT)      // 2048
#define INV_S   0.1f
#define CULL_R  11.0f               // > sqrt(115.13)=10.73 -> clip-identical

typedef unsigned long long ull;

__device__ __forceinline__ ull f2add(ull a, ull b) {
    ull r; asm("add.rn.f32x2 %0,%1,%2;" : "=l"(r) : "l"(a), "l"(b)); return r;
}
__device__ __forceinline__ ull f2mul(ull a, ull b) {
    ull r; asm("mul.rn.f32x2 %0,%1,%2;" : "=l"(r) : "l"(a), "l"(b)); return r;
}
__device__ __forceinline__ ull f2fma(ull a, ull b, ull c) {
    ull r; asm("fma.rn.f32x2 %0,%1,%2,%3;" : "=l"(r) : "l"(a), "l"(b), "l"(c)); return r;
}
__device__ __forceinline__ ull fpack(float lo, float hi) {
    ull r; asm("mov.b64 %0,{%1,%2};" : "=l"(r) : "f"(lo), "f"(hi)); return r;
}
__device__ __forceinline__ void funpack(float& lo, float& hi, ull v) {
    asm("mov.b64 {%0,%1},%2;" : "=f"(lo), "=f"(hi) : "l"(v));
}
__device__ __forceinline__ float mulsat(float a, float b) {
    float r; asm("mul.rn.sat.f32 %0,%1,%2;" : "=f"(r) : "f"(a), "f"(b)); return r;
}

// Scratch (no allocations allowed)
__device__ float g_part[NBLOCKS*3];
__device__ int   g_count = 0;

__global__ __launch_bounds__(THREADS) void fused_kernel(
    const float* __restrict__ preds,
    const float* __restrict__ masks,
    const float* __restrict__ bboxes,
    float* __restrict__ out)
{
    int b     = blockIdx.x;
    int n     = b >> 4;
    int chunk = b & 15;
    int tid   = threadIdx.x;
    int wid   = tid >> 5, lid = tid & 31;

    // DENSE distance list, pre-packed f32x2 pairs
    __shared__ ulonglong2 s_d0[NV+4];    // {(-ax,-ax), (abx,abx)}
    __shared__ ulonglong2 s_d1[NV+4];    // {(-abx,-abx), (-aby,-aby)}
    __shared__ ulonglong2 s_d2[NV+4];    // {(-ay,-ay), (aby,aby)}
    __shared__ float s_inv[NV+4];        // invd
    // DENSE parity-only list
    __shared__ float4 s_pp[NV+2];        // {ay, by, slope, ax}
    __shared__ float  s_vx[NV], s_vy[NV];
    __shared__ float  s_red[16];
    __shared__ float  s_ub[4];
    __shared__ int    s_wcnt[4], s_wcnp[4];
    __shared__ int    s_last;

    // ---- per-block prep: union box + normalized verts ----
    float2 pv = ((const float2*)preds)[n*NV + tid];
    float x = pv.x, y = pv.y;
    float mnx = x, mny = y, mxx = x, mxy = y;
#pragma unroll
    for (int o = 16; o > 0; o >>= 1) {
        mnx = fminf(mnx, __shfl_xor_sync(0xffffffffu, mnx, o));
        mny = fminf(mny, __shfl_xor_sync(0xffffffffu, mny, o));
        mxx = fmaxf(mxx, __shfl_xor_sync(0xffffffffu, mxx, o));
        mxy = fmaxf(mxy, __shfl_xor_sync(0xffffffffu, mxy, o));
    }
    if (lid == 0) { s_red[wid] = mnx; s_red[4+wid] = mny; s_red[8+wid] = mxx; s_red[12+wid] = mxy; }
    __syncthreads();
    if (tid == 0) {
        float a = fminf(fminf(s_red[0],  s_red[1]),  fminf(s_red[2],  s_red[3]));
        float c = fminf(fminf(s_red[4],  s_red[5]),  fminf(s_red[6],  s_red[7]));
        float d = fmaxf(fmaxf(s_red[8],  s_red[9]),  fmaxf(s_red[10], s_red[11]));
        float e = fmaxf(fmaxf(s_red[12], s_red[13]), fmaxf(s_red[14], s_red[15]));
        s_ub[0] = fminf(a, bboxes[n*4+0]);
        s_ub[1] = fminf(c, bboxes[n*4+1]);
        s_ub[2] = fmaxf(d, bboxes[n*4+2]);
        s_ub[3] = fmaxf(e, bboxes[n*4+3]);
    }
    __syncthreads();
    float ub0 = s_ub[0], ub1 = s_ub[1], ub2 = s_ub[2], ub3 = s_ub[3];
    float vx = (x - ub0) / (ub2 - ub0) * (float)RES - 0.5f;
    float vy = (y - ub1) / (ub3 - ub1) * (float)RES - 0.5f;
    s_vx[tid] = vx; s_vy[tid] = vy;
    __syncthreads();

    // ---- segment params + two block-level culls + dense compaction ----
    float ax, ay, abx, aby, invd, slope, byv;
    bool keep_d, keep_p;
    {
        int t1 = (tid + 1) & (NV - 1);
        ax = vx; ay = vy;
        float bx = s_vx[t1]; byv = s_vy[t1];
        abx = bx - ax; aby = byv - ay;
        invd = 1.0f / (abx*abx + aby*aby + 1e-12f);
        float sdy = (aby == 0.0f) ? 1.0f : aby;
        slope = abx / sdy;
        float ymin = fminf(ay, byv);
        float ymax = fmaxf(ay, byv);
        float r0f = (float)(chunk * 4);
        float r1f = (float)(chunk * 4 + 3);
        keep_d = (ymax >= r0f - CULL_R) && (ymin <= r1f + CULL_R);
        keep_p = (ymax > r0f) && (ymin <= r1f);
    }
    unsigned bal_d = __ballot_sync(0xffffffffu, keep_d);
    unsigned bal_p = __ballot_sync(0xffffffffu, keep_p);
    if (lid == 0) { s_wcnt[wid] = __popc(bal_d); s_wcnp[wid] = __popc(bal_p); }
    __syncthreads();
    int cnt_d = s_wcnt[0] + s_wcnt[1] + s_wcnt[2] + s_wcnt[3];
    int cnt_p = s_wcnp[0] + s_wcnp[1] + s_wcnp[2] + s_wcnp[3];
    {
        int wb_d = 0, wb_p = 0;
#pragma unroll
        for (int w = 0; w < 4; w++) {
            wb_d += (w < wid) ? s_wcnt[w] : 0;
            wb_p += (w < wid) ? s_wcnp[w] : 0;
        }
        if (keep_d) {
            int pos = wb_d + __popc(bal_d & ((1u << lid) - 1u));
            ulonglong2 v0; v0.x = fpack(-ax, -ax);   v0.y = fpack(abx, abx);
            ulonglong2 v1; v1.x = fpack(-abx, -abx); v1.y = fpack(-aby, -aby);
            ulonglong2 v2; v2.x = fpack(-ay, -ay);   v2.y = fpack(aby, aby);
            s_d0[pos] = v0; s_d1[pos] = v1; s_d2[pos] = v2;
            s_inv[pos] = invd;
        }
        if (keep_p) {
            int pos = wb_p + __popc(bal_p & ((1u << lid) - 1u));
            s_pp[pos]  = make_float4(ay, byv, slope, ax);
        }
        if (tid < 4) {
            // distance sentinels x4: abx=aby=0, ay=-1e30 -> d^2 = inf
            int s = cnt_d + tid;
            ulonglong2 z; z.x = 0ull; z.y = 0ull;
            ulonglong2 v2; v2.x = fpack(-1.0e30f, -1.0e30f); v2.y = 0ull;
            s_d0[s] = z; s_d1[s] = z; s_d2[s] = v2;
            s_inv[s] = 0.0f;
        }
        if (tid < 2) {
            // parity sentinels: both endpoints above every row -> cond false
            s_pp[cnt_p + tid] = make_float4(1.0e30f, 1.0e30f, 0.f, 0.f);
        }
    }
    int cntd = (cnt_d + 3) & ~3;   // multiple of 4 for x4 unroll
    int cntp = (cnt_p + 1) & ~1;
    __syncthreads();

    // ---- rasterize: one row, 2 consecutive pixels per thread ----
    int row   = chunk * 4 + (tid >> 5);
    int xbase = lid * PPT;
    float pyf = (float)row;
    float xbf = (float)xbase;
    ull pyf2  = fpack(pyf, pyf);
    ull px2   = fpack(xbf, xbf + 1.0f);

    float d2min0 = 3.4e38f, d2min1 = 3.4e38f;

    // main loop: distance only, pre-packed params, x4 unroll (sequential LDS)
    for (int v = 0; v < cntd; v += 4) {
#pragma unroll
        for (int u = 0; u < 4; u++) {
            int vv = v + u;
            ulonglong2 D0 = s_d0[vv];
            ulonglong2 D1 = s_d1[vv];
            ulonglong2 D2 = s_d2[vv];
            float sinvd = s_inv[vv];

            ull pay2    = f2add(pyf2, D2.x);       // {pay,pay}
            ull payaby2 = f2mul(pay2, D2.y);       // {pay*aby, pay*aby}

            ull pax2 = f2add(px2, D0.x);
            ull dot2 = f2fma(pax2, D0.y, payaby2);
            float d0, d1; funpack(d0, d1, dot2);
            float t0 = mulsat(d0, sinvd);
            float t1 = mulsat(d1, sinvd);
            ull tc2 = fpack(t0, t1);
            ull dx2 = f2fma(tc2, D1.x, pax2);
            ull dy2 = f2fma(tc2, D1.y, pay2);
            ull e2  = f2mul(dy2, dy2);
            ull q2  = f2fma(dx2, dx2, e2);
            float q0, q1; funpack(q0, q1, q2);
            d2min0 = fminf(d2min0, q0);
            d2min1 = fminf(d2min1, q1);
        }
    }

    // parity loop: tiny straddle list
    unsigned crossbits = 0;
    for (int v = 0; v < cntp; v += 2) {
#pragma unroll
        for (int u = 0; u < 2; u++) {
            float4 q = s_pp[v + u];     // {ay, by, slope, ax}
            float pay  = pyf - q.x;
            bool  cond = (q.x > pyf) != (q.y > pyf);
            float xint = fmaf(pay, q.z, q.w);
            int   kk   = (int)ceilf(xint - xbf);
            kk = min(max(kk, 0), PPT);
            unsigned m = (1u << kk) - 1u;
            crossbits ^= cond ? m : 0u;
        }
    }

    // ---- sigmoid + target bilinear + dice partials ----
    const float* __restrict__ mask = masks + (size_t)n * IMG * IMG;
    float ys = ub1 + (ub3 - ub1) * ((pyf + 0.5f) * (1.0f/(float)RES)) - 0.5f;
    float y0 = floorf(ys);
    float wy = ys - y0;
    int y0i = min(max((int)y0, 0), IMG-1);
    int y1i = min(y0i + 1, IMG-1);
    const float* r0p = mask + y0i*IMG;
    const float* r1p = mask + y1i*IMG;

    float inter = 0.0f, sp = 0.0f, st = 0.0f;
#pragma unroll
    for (int k = 0; k < PPT; k++) {
        float dmin = (k == 0) ? d2min0 : d2min1;
        float sign = (crossbits >> k) & 1u ? 1.0f : -1.0f;
        float xarg = sign * dmin * INV_S;
        float pred = 1.0f / (1.0f + __expf(-xarg));
        pred = fminf(fmaxf(pred, 1e-5f), 0.99999f);

        float xs = ub0 + (ub2 - ub0) * ((xbf + (float)k + 0.5f) * (1.0f/(float)RES)) - 0.5f;
        float x0 = floorf(xs);
        float wx = xs - x0;
        int x0i = min(max((int)x0, 0), IMG-1);
        int x1i = min(x0i + 1, IMG-1);
        float m00 = r0p[x0i], m01 = r0p[x1i];
        float m10 = r1p[x0i], m11 = r1p[x1i];
        float val = (1.0f - wy) * ((1.0f - wx)*m00 + wx*m01)
                  +          wy * ((1.0f - wx)*m10 + wx*m11);
        float tgt = (val >= 0.5f) ? 1.0f : 0.0f;

        inter += pred * tgt;
        sp    += pred;
        st    += tgt;
    }

    // ---- deterministic block reduce ----
#pragma unroll
    for (int o = 16; o > 0; o >>= 1) {
        inter += __shfl_down_sync(0xffffffffu, inter, o);
        sp    += __shfl_down_sync(0xffffffffu, sp,    o);
        st    += __shfl_down_sync(0xffffffffu, st,    o);
    }
    __shared__ float r_i[4], r_p[4], r_t[4];
    if (lid == 0) { r_i[wid] = inter; r_p[wid] = sp; r_t[wid] = st; }
    __syncthreads();
    if (tid == 0) {
        float ti = r_i[0]+r_i[1]+r_i[2]+r_i[3];
        float tp = r_p[0]+r_p[1]+r_p[2]+r_p[3];
        float tt = r_t[0]+r_t[1]+r_t[2]+r_t[3];
        g_part[b*3+0] = ti;
        g_part[b*3+1] = tp;
        g_part[b*3+2] = tt;
        __threadfence();
        int old = atomicAdd(&g_count, 1);
        s_last = (old == NBLOCKS - 1) ? 1 : 0;
    }
    __syncthreads();

    // ---- last block finalizes: per-instance dice + mean ----
    if (s_last) {
        float fi = 0.0f, fp = 0.0f, ft = 0.0f;   // instance = tid
#pragma unroll
        for (int c = 0; c < SPLIT; c++) {
            int slot = ((tid << 4) + c) * 3;
            fi += __ldcg(&g_part[slot+0]);
            fp += __ldcg(&g_part[slot+1]);
            ft += __ldcg(&g_part[slot+2]);
        }
        float loss = 1.0f - (2.0f*fi + 1.0f) / (fp + ft + 1.0f);
        s_vx[tid] = loss;                        // reuse smem as scratch
        __syncthreads();
        for (int o = THREADS/2; o > 0; o >>= 1) {
            if (tid < o) s_vx[tid] += s_vx[tid + o];
            __syncthreads();
        }
        if (tid == 0) {
            out[0] = s_vx[0] * (1.0f / (float)N_INST);
            g_count = 0;                          // reset for next graph replay
        }
    }
}

extern "C" void kernel_launch(void* const* d_in, const int* in_sizes, int n_in,
                              void* d_out, int out_size) {
    const float* preds  = (const float*)d_in[0];
    const float* masks  = (const float*)d_in[1];
    const float* bboxes = (const float*)d_in[2];
    float* out = (float*)d_out;

    fused_kernel<<<NBLOCKS, THREADS>>>(preds, masks, bboxes, out);
}

// round 15
// speedup vs baseline: 1.0239x; 1.0239x over previous
#include <cuda_runtime.h>
#include <math.h>

#define N_INST 128
#define NV     128
#define IMG    512
#define RES    64
#define SPLIT  16                   // 16 blocks per instance, 4 rows each
#define THREADS 128
#define PPT     2                   // 2 consecutive x per thread (one row)
#define NPAIR   (PPT/2)             // 1
#define NBLOCKS (N_INST*SPLIT)      // 2048
#define INV_S   0.1f
#define CULL_R  11.0f               // > sqrt(115.13)=10.73 -> clip-identical

typedef unsigned long long ull;

__device__ __forceinline__ ull f2add(ull a, ull b) {
    ull r; asm("add.rn.f32x2 %0,%1,%2;" : "=l"(r) : "l"(a), "l"(b)); return r;
}
__device__ __forceinline__ ull f2mul(ull a, ull b) {
    ull r; asm("mul.rn.f32x2 %0,%1,%2;" : "=l"(r) : "l"(a), "l"(b)); return r;
}
__device__ __forceinline__ ull f2fma(ull a, ull b, ull c) {
    ull r; asm("fma.rn.f32x2 %0,%1,%2,%3;" : "=l"(r) : "l"(a), "l"(b), "l"(c)); return r;
}
__device__ __forceinline__ ull fpack(float lo, float hi) {
    ull r; asm("mov.b64 %0,{%1,%2};" : "=l"(r) : "f"(lo), "f"(hi)); return r;
}
__device__ __forceinline__ void funpack(float& lo, float& hi, ull v) {
    asm("mov.b64 {%0,%1},%2;" : "=f"(lo), "=f"(hi) : "l"(v));
}
__device__ __forceinline__ float mulsat(float a, float b) {
    float r; asm("mul.rn.sat.f32 %0,%1,%2;" : "=f"(r) : "f"(a), "f"(b)); return r;
}

// Scratch (no allocations allowed)
__device__ float g_part[NBLOCKS*3];
__device__ int   g_count = 0;

__global__ __launch_bounds__(THREADS) void fused_kernel(
    const float* __restrict__ preds,
    const float* __restrict__ masks,
    const float* __restrict__ bboxes,
    float* __restrict__ out)
{
    int b     = blockIdx.x;
    int n     = b >> 4;
    int chunk = b & 15;
    int tid   = threadIdx.x;
    int wid   = tid >> 5, lid = tid & 31;

    // DENSE distance list, pre-packed f32x2 pairs
    __shared__ ulonglong2 s_d0[NV+4];    // {(-ax,-ax), (abx,abx)}
    __shared__ ulonglong2 s_d1[NV+4];    // {(-abx,-abx), (-aby,-aby)}
    __shared__ ulonglong2 s_d2[NV+4];    // {(-ay,-ay), (aby,aby)}
    __shared__ float s_inv[NV+4];        // invd
    // DENSE parity-only list
    __shared__ float4 s_pp[NV+2];        // {ay, by, slope, ax}
    __shared__ float  s_vx[NV], s_vy[NV];
    __shared__ float  s_red[16];
    __shared__ float  s_ub[4];
    __shared__ int    s_wcnt[4], s_wcnp[4];
    __shared__ int    s_last;

    // ---- per-block prep: union box + normalized verts ----
    float2 pv = ((const float2*)preds)[n*NV + tid];
    float x = pv.x, y = pv.y;
    float mnx = x, mny = y, mxx = x, mxy = y;
#pragma unroll
    for (int o = 16; o > 0; o >>= 1) {
        mnx = fminf(mnx, __shfl_xor_sync(0xffffffffu, mnx, o));
        mny = fminf(mny, __shfl_xor_sync(0xffffffffu, mny, o));
        mxx = fmaxf(mxx, __shfl_xor_sync(0xffffffffu, mxx, o));
        mxy = fmaxf(mxy, __shfl_xor_sync(0xffffffffu, mxy, o));
    }
    if (lid == 0) { s_red[wid] = mnx; s_red[4+wid] = mny; s_red[8+wid] = mxx; s_red[12+wid] = mxy; }
    __syncthreads();
    if (tid == 0) {
        float a = fminf(fminf(s_red[0],  s_red[1]),  fminf(s_red[2],  s_red[3]));
        float c = fminf(fminf(s_red[4],  s_red[5]),  fminf(s_red[6],  s_red[7]));
        float d = fmaxf(fmaxf(s_red[8],  s_red[9]),  fmaxf(s_red[10], s_red[11]));
        float e = fmaxf(fmaxf(s_red[12], s_red[13]), fmaxf(s_red[14], s_red[15]));
        s_ub[0] = fminf(a, bboxes[n*4+0]);
        s_ub[1] = fminf(c, bboxes[n*4+1]);
        s_ub[2] = fmaxf(d, bboxes[n*4+2]);
        s_ub[3] = fmaxf(e, bboxes[n*4+3]);
    }
    __syncthreads();
    float ub0 = s_ub[0], ub1 = s_ub[1], ub2 = s_ub[2], ub3 = s_ub[3];
    float vx = (x - ub0) / (ub2 - ub0) * (float)RES - 0.5f;
    float vy = (y - ub1) / (ub3 - ub1) * (float)RES - 0.5f;
    s_vx[tid] = vx; s_vy[tid] = vy;
    __syncthreads();

    // ---- segment params + two block-level culls + dense compaction ----
    float ax, ay, abx, aby, invd, slope, byv;
    bool keep_d, keep_p;
    {
        int t1 = (tid + 1) & (NV - 1);
        ax = vx; ay = vy;
        float bx = s_vx[t1]; byv = s_vy[t1];
        abx = bx - ax; aby = byv - ay;
        invd = 1.0f / (abx*abx + aby*aby + 1e-12f);
        float sdy = (aby == 0.0f) ? 1.0f : aby;
        slope = abx / sdy;
        float ymin = fminf(ay, byv);
        float ymax = fmaxf(ay, byv);
        float r0f = (float)(chunk * 4);
        float r1f = (float)(chunk * 4 + 3);
        keep_d = (ymax >= r0f - CULL_R) && (ymin <= r1f + CULL_R);
        keep_p = (ymax > r0f) && (ymin <= r1f);
    }
    unsigned bal_d = __ballot_sync(0xffffffffu, keep_d);
    unsigned bal_p = __ballot_sync(0xffffffffu, keep_p);
    if (lid == 0) { s_wcnt[wid] = __popc(bal_d); s_wcnp[wid] = __popc(bal_p); }
    __syncthreads();
    int cnt_d = s_wcnt[0] + s_wcnt[1] + s_wcnt[2] + s_wcnt[3];
    int cnt_p = s_wcnp[0] + s_wcnp[1] + s_wcnp[2] + s_wcnp[3];
    {
        int wb_d = 0, wb_p = 0;
#pragma unroll
        for (int w = 0; w < 4; w++) {
            wb_d += (w < wid) ? s_wcnt[w] : 0;
            wb_p += (w < wid) ? s_wcnp[w] : 0;
        }
        if (keep_d) {
            int pos = wb_d + __popc(bal_d & ((1u << lid) - 1u));
            ulonglong2 v0; v0.x = fpack(-ax, -ax);   v0.y = fpack(abx, abx);
            ulonglong2 v1; v1.x = fpack(-abx, -abx); v1.y = fpack(-aby, -aby);
            ulonglong2 v2; v2.x = fpack(-ay, -ay);   v2.y = fpack(aby, aby);
            s_d0[pos] = v0; s_d1[pos] = v1; s_d2[pos] = v2;
            s_inv[pos] = invd;
        }
        if (keep_p) {
            int pos = wb_p + __popc(bal_p & ((1u << lid) - 1u));
            s_pp[pos]  = make_float4(ay, byv, slope, ax);
        }
        if (tid < 4) {
            // distance sentinels x4: abx=aby=0, ay=-1e30 -> d^2 = inf
            int s = cnt_d + tid;
            ulonglong2 z; z.x = 0ull; z.y = 0ull;
            ulonglong2 v2; v2.x = fpack(-1.0e30f, -1.0e30f); v2.y = 0ull;
            s_d0[s] = z; s_d1[s] = z; s_d2[s] = v2;
            s_inv[s] = 0.0f;
        }
        if (tid < 2) {
            // parity sentinels: both endpoints above every row -> cond false
            s_pp[cnt_p + tid] = make_float4(1.0e30f, 1.0e30f, 0.f, 0.f);
        }
    }
    int cntd = (cnt_d + 3) & ~3;   // multiple of 4 for x4 unroll
    int cntp = (cnt_p + 1) & ~1;
    __syncthreads();

    // ---- rasterize: one row, 2 consecutive pixels per thread ----
    int row   = chunk * 4 + (tid >> 5);
    int xbase = lid * PPT;
    float pyf = (float)row;
    float xbf = (float)xbase;
    ull pyf2  = fpack(pyf, pyf);
    ull px2   = fpack(xbf, xbf + 1.0f);

    float d2min0 = 3.4e38f, d2min1 = 3.4e38f;

    // main loop: distance only, pre-packed params, x4 unroll (sequential LDS)
    for (int v = 0; v < cntd; v += 4) {
#pragma unroll
        for (int u = 0; u < 4; u++) {
            int vv = v + u;
            ulonglong2 D0 = s_d0[vv];
            ulonglong2 D1 = s_d1[vv];
            ulonglong2 D2 = s_d2[vv];
            float sinvd = s_inv[vv];

            ull pay2    = f2add(pyf2, D2.x);       // {pay,pay}
            ull payaby2 = f2mul(pay2, D2.y);       // {pay*aby, pay*aby}

            ull pax2 = f2add(px2, D0.x);
            ull dot2 = f2fma(pax2, D0.y, payaby2);
            float d0, d1; funpack(d0, d1, dot2);
            float t0 = mulsat(d0, sinvd);
            float t1 = mulsat(d1, sinvd);
            ull tc2 = fpack(t0, t1);
            ull dx2 = f2fma(tc2, D1.x, pax2);
            ull dy2 = f2fma(tc2, D1.y, pay2);
            ull e2  = f2mul(dy2, dy2);
            ull q2  = f2fma(dx2, dx2, e2);
            float q0, q1; funpack(q0, q1, q2);
            d2min0 = fminf(d2min0, q0);
            d2min1 = fminf(d2min1, q1);
        }
    }

    // parity loop: tiny straddle list
    unsigned crossbits = 0;
    for (int v = 0; v < cntp; v += 2) {
#pragma unroll
        for (int u = 0; u < 2; u++) {
            float4 q = s_pp[v + u];     // {ay, by, slope, ax}
            float pay  = pyf - q.x;
            bool  cond = (q.x > pyf) != (q.y > pyf);
            float xint = fmaf(pay, q.z, q.w);
            int   kk   = (int)ceilf(xint - xbf);
            kk = min(max(kk, 0), PPT);
            unsigned m = (1u << kk) - 1u;
            crossbits ^= cond ? m : 0u;
        }
    }

    // ---- sigmoid + target bilinear + dice partials ----
    const float* __restrict__ mask = masks + (size_t)n * IMG * IMG;
    float ys = ub1 + (ub3 - ub1) * ((pyf + 0.5f) * (1.0f/(float)RES)) - 0.5f;
    float y0 = floorf(ys);
    float wy = ys - y0;
    int y0i = min(max((int)y0, 0), IMG-1);
    int y1i = min(y0i + 1, IMG-1);
    const float* r0p = mask + y0i*IMG;
    const float* r1p = mask + y1i*IMG;

    float inter = 0.0f, sp = 0.0f, st = 0.0f;
#pragma unroll
    for (int k = 0; k < PPT; k++) {
        float dmin = (k == 0) ? d2min0 : d2min1;
        float sign = (crossbits >> k) & 1u ? 1.0f : -1.0f;
        float xarg = sign * dmin * INV_S;
        float pred = 1.0f / (1.0f + __expf(-xarg));
        pred = fminf(fmaxf(pred, 1e-5f), 0.99999f);

        float xs = ub0 + (ub2 - ub0) * ((xbf + (float)k + 0.5f) * (1.0f/(float)RES)) - 0.5f;
        float x0 = floorf(xs);
        float wx = xs - x0;
        int x0i = min(max((int)x0, 0), IMG-1);
        int x1i = min(x0i + 1, IMG-1);
        float m00 = r0p[x0i], m01 = r0p[x1i];
        float m10 = r1p[x0i], m11 = r1p[x1i];
        float val = (1.0f - wy) * ((1.0f - wx)*m00 + wx*m01)
                  +          wy * ((1.0f - wx)*m10 + wx*m11);
        float tgt = (val >= 0.5f) ? 1.0f : 0.0f;

        inter += pred * tgt;
        sp    += pred;
        st    += tgt;
    }

    // ---- deterministic block reduce ----
#pragma unroll
    for (int o = 16; o > 0; o >>= 1) {
        inter += __shfl_down_sync(0xffffffffu, inter, o);
        sp    += __shfl_down_sync(0xffffffffu, sp,    o);
        st    += __shfl_down_sync(0xffffffffu, st,    o);
    }
    __shared__ float r_i[4], r_p[4], r_t[4];
    if (lid == 0) { r_i[wid] = inter; r_p[wid] = sp; r_t[wid] = st; }
    __syncthreads();
    if (tid == 0) {
        float ti = r_i[0]+r_i[1]+r_i[2]+r_i[3];
        float tp = r_p[0]+r_p[1]+r_p[2]+r_p[3];
        float tt = r_t[0]+r_t[1]+r_t[2]+r_t[3];
        g_part[b*3+0] = ti;
        g_part[b*3+1] = tp;
        g_part[b*3+2] = tt;
        __threadfence();
        int old = atomicAdd(&g_count, 1);
        s_last = (old == NBLOCKS - 1) ? 1 : 0;
    }
    __syncthreads();

    // ---- last block finalizes: per-instance dice + mean ----
    if (s_last) {
        float fi = 0.0f, fp = 0.0f, ft = 0.0f;   // instance = tid
#pragma unroll
        for (int c = 0; c < SPLIT; c++) {
            int slot = ((tid << 4) + c) * 3;
            fi += __ldcg(&g_part[slot+0]);
            fp += __ldcg(&g_part[slot+1]);
            ft += __ldcg(&g_part[slot+2]);
        }
        float loss = 1.0f - (2.0f*fi + 1.0f) / (fp + ft + 1.0f);
        s_vx[tid] = loss;                        // reuse smem as scratch
        __syncthreads();
        for (int o = THREADS/2; o > 0; o >>= 1) {
            if (tid < o) s_vx[tid] += s_vx[tid + o];
            __syncthreads();
        }
        if (tid == 0) {
            out[0] = s_vx[0] * (1.0f / (float)N_INST);
            g_count = 0;                          // reset for next graph replay
        }
    }
}

extern "C" void kernel_launch(void* const* d_in, const int* in_sizes, int n_in,
                              void* d_out, int out_size) {
    const float* preds  = (const float*)d_in[0];
    const float* masks  = (const float*)d_in[1];
    const float* bboxes = (const float*)d_in[2];
    float* out = (float*)d_out;

    fused_kernel<<<NBLOCKS, THREADS>>>(preds, masks, bboxes, out);
}

// round 16
// speedup vs baseline: 1.0329x; 1.0088x over previous
#include <cuda_runtime.h>
#include <math.h>

#define N_INST 128
#define NV     128
#define IMG    512
#define RES    64
#define SPLIT  16                   // 16 blocks per instance, 4 rows each
#define THREADS 128
#define PPT     2                   // 2 consecutive x per thread (one row)
#define NPAIR   (PPT/2)             // 1
#define NBLOCKS (N_INST*SPLIT)      // 2048
#define INV_S   0.1f
#define CULL_R  11.0f               // > sqrt(115.13)=10.73 -> clip-identical

typedef unsigned long long ull;

__device__ __forceinline__ ull f2add(ull a, ull b) {
    ull r; asm("add.rn.f32x2 %0,%1,%2;" : "=l"(r) : "l"(a), "l"(b)); return r;
}
__device__ __forceinline__ ull f2mul(ull a, ull b) {
    ull r; asm("mul.rn.f32x2 %0,%1,%2;" : "=l"(r) : "l"(a), "l"(b)); return r;
}
__device__ __forceinline__ ull f2fma(ull a, ull b, ull c) {
    ull r; asm("fma.rn.f32x2 %0,%1,%2,%3;" : "=l"(r) : "l"(a), "l"(b), "l"(c)); return r;
}
__device__ __forceinline__ ull fpack(float lo, float hi) {
    ull r; asm("mov.b64 %0,{%1,%2};" : "=l"(r) : "f"(lo), "f"(hi)); return r;
}
__device__ __forceinline__ void funpack(float& lo, float& hi, ull v) {
    asm("mov.b64 {%0,%1},%2;" : "=f"(lo), "=f"(hi) : "l"(v));
}
__device__ __forceinline__ float mulsat(float a, float b) {
    float r; asm("mul.rn.sat.f32 %0,%1,%2;" : "=f"(r) : "f"(a), "f"(b)); return r;
}

// Scratch (no allocations allowed)
__device__ float g_part[NBLOCKS*3];
__device__ int   g_count = 0;

__global__ __launch_bounds__(THREADS) void fused_kernel(
    const float* __restrict__ preds,
    const float* __restrict__ masks,
    const float* __restrict__ bboxes,
    float* __restrict__ out)
{
    int b     = blockIdx.x;
    int n     = b >> 4;
    int chunk = b & 15;
    int tid   = threadIdx.x;
    int wid   = tid >> 5, lid = tid & 31;

    // DENSE distance list, pre-packed f32x2 pairs
    __shared__ ulonglong2 s_d0[NV+4];    // {(-ax,-ax), (abx,abx)}
    __shared__ ulonglong2 s_d1[NV+4];    // {(-abx,-abx), (-aby,-aby)}
    __shared__ ulonglong2 s_d2[NV+4];    // {(-ay,-ay), (aby,aby)}
    __shared__ float s_inv[NV+4];        // invd
    // DENSE parity-only list
    __shared__ float4 s_pp[NV+2];        // {ay, by, slope, ax}
    __shared__ float  s_vx[NV], s_vy[NV];
    __shared__ float  s_red[16];
    __shared__ float  s_ub[4];
    __shared__ int    s_wcnt[4], s_wcnp[4];
    __shared__ int    s_last;

    // ---- per-block prep: union box + normalized verts ----
    float2 pv = ((const float2*)preds)[n*NV + tid];
    float x = pv.x, y = pv.y;
    float mnx = x, mny = y, mxx = x, mxy = y;
#pragma unroll
    for (int o = 16; o > 0; o >>= 1) {
        mnx = fminf(mnx, __shfl_xor_sync(0xffffffffu, mnx, o));
        mny = fminf(mny, __shfl_xor_sync(0xffffffffu, mny, o));
        mxx = fmaxf(mxx, __shfl_xor_sync(0xffffffffu, mxx, o));
        mxy = fmaxf(mxy, __shfl_xor_sync(0xffffffffu, mxy, o));
    }
    if (lid == 0) { s_red[wid] = mnx; s_red[4+wid] = mny; s_red[8+wid] = mxx; s_red[12+wid] = mxy; }
    __syncthreads();
    if (tid == 0) {
        float a = fminf(fminf(s_red[0],  s_red[1]),  fminf(s_red[2],  s_red[3]));
        float c = fminf(fminf(s_red[4],  s_red[5]),  fminf(s_red[6],  s_red[7]));
        float d = fmaxf(fmaxf(s_red[8],  s_red[9]),  fmaxf(s_red[10], s_red[11]));
        float e = fmaxf(fmaxf(s_red[12], s_red[13]), fmaxf(s_red[14], s_red[15]));
        s_ub[0] = fminf(a, bboxes[n*4+0]);
        s_ub[1] = fminf(c, bboxes[n*4+1]);
        s_ub[2] = fmaxf(d, bboxes[n*4+2]);
        s_ub[3] = fmaxf(e, bboxes[n*4+3]);
    }
    __syncthreads();
    float ub0 = s_ub[0], ub1 = s_ub[1], ub2 = s_ub[2], ub3 = s_ub[3];
    float vx = (x - ub0) / (ub2 - ub0) * (float)RES - 0.5f;
    float vy = (y - ub1) / (ub3 - ub1) * (float)RES - 0.5f;
    s_vx[tid] = vx; s_vy[tid] = vy;
    __syncthreads();

    // ---- segment params + two block-level culls + dense compaction ----
    float ax, ay, abx, aby, invd, slope, byv;
    bool keep_d, keep_p;
    {
        int t1 = (tid + 1) & (NV - 1);
        ax = vx; ay = vy;
        float bx = s_vx[t1]; byv = s_vy[t1];
        abx = bx - ax; aby = byv - ay;
        invd = 1.0f / (abx*abx + aby*aby + 1e-12f);
        float sdy = (aby == 0.0f) ? 1.0f : aby;
        slope = abx / sdy;
        float ymin = fminf(ay, byv);
        float ymax = fmaxf(ay, byv);
        float r0f = (float)(chunk * 4);
        float r1f = (float)(chunk * 4 + 3);
        keep_d = (ymax >= r0f - CULL_R) && (ymin <= r1f + CULL_R);
        keep_p = (ymax > r0f) && (ymin <= r1f);
    }
    unsigned bal_d = __ballot_sync(0xffffffffu, keep_d);
    unsigned bal_p = __ballot_sync(0xffffffffu, keep_p);
    if (lid == 0) { s_wcnt[wid] = __popc(bal_d); s_wcnp[wid] = __popc(bal_p); }
    __syncthreads();
    int cnt_d = s_wcnt[0] + s_wcnt[1] + s_wcnt[2] + s_wcnt[3];
    int cnt_p = s_wcnp[0] + s_wcnp[1] + s_wcnp[2] + s_wcnp[3];
    {
        int wb_d = 0, wb_p = 0;
#pragma unroll
        for (int w = 0; w < 4; w++) {
            wb_d += (w < wid) ? s_wcnt[w] : 0;
            wb_p += (w < wid) ? s_wcnp[w] : 0;
        }
        if (keep_d) {
            int pos = wb_d + __popc(bal_d & ((1u << lid) - 1u));
            ulonglong2 v0; v0.x = fpack(-ax, -ax);   v0.y = fpack(abx, abx);
            ulonglong2 v1; v1.x = fpack(-abx, -abx); v1.y = fpack(-aby, -aby);
            ulonglong2 v2; v2.x = fpack(-ay, -ay);   v2.y = fpack(aby, aby);
            s_d0[pos] = v0; s_d1[pos] = v1; s_d2[pos] = v2;
            s_inv[pos] = invd;
        }
        if (keep_p) {
            int pos = wb_p + __popc(bal_p & ((1u << lid) - 1u));
            s_pp[pos]  = make_float4(ay, byv, slope, ax);
        }
        if (tid < 4) {
            // distance sentinels x4: abx=aby=0, ay=-1e30 -> d^2 = inf
            int s = cnt_d + tid;
            ulonglong2 z; z.x = 0ull; z.y = 0ull;
            ulonglong2 v2; v2.x = fpack(-1.0e30f, -1.0e30f); v2.y = 0ull;
            s_d0[s] = z; s_d1[s] = z; s_d2[s] = v2;
            s_inv[s] = 0.0f;
        }
        if (tid < 2) {
            // parity sentinels: both endpoints above every row -> cond false
            s_pp[cnt_p + tid] = make_float4(1.0e30f, 1.0e30f, 0.f, 0.f);
        }
    }
    int cntd = (cnt_d + 3) & ~3;   // multiple of 4 for x4 unroll
    int cntp = (cnt_p + 1) & ~1;
    __syncthreads();

    // ---- rasterize: one row, 2 consecutive pixels per thread ----
    int row   = chunk * 4 + (tid >> 5);
    int xbase = lid * PPT;
    float pyf = (float)row;
    float xbf = (float)xbase;
    ull pyf2  = fpack(pyf, pyf);
    ull px2   = fpack(xbf, xbf + 1.0f);

    float d2min0 = 3.4e38f, d2min1 = 3.4e38f;

    // main loop: distance only, pre-packed params, x4 unroll (sequential LDS)
    for (int v = 0; v < cntd; v += 4) {
#pragma unroll
        for (int u = 0; u < 4; u++) {
            int vv = v + u;
            ulonglong2 D0 = s_d0[vv];
            ulonglong2 D1 = s_d1[vv];
            ulonglong2 D2 = s_d2[vv];
            float sinvd = s_inv[vv];

            ull pay2    = f2add(pyf2, D2.x);       // {pay,pay}
            ull payaby2 = f2mul(pay2, D2.y);       // {pay*aby, pay*aby}

            ull pax2 = f2add(px2, D0.x);
            ull dot2 = f2fma(pax2, D0.y, payaby2);
            float d0, d1; funpack(d0, d1, dot2);
            float t0 = mulsat(d0, sinvd);
            float t1 = mulsat(d1, sinvd);
            ull tc2 = fpack(t0, t1);
            ull dx2 = f2fma(tc2, D1.x, pax2);
            ull dy2 = f2fma(tc2, D1.y, pay2);
            ull e2  = f2mul(dy2, dy2);
            ull q2  = f2fma(dx2, dx2, e2);
            float q0, q1; funpack(q0, q1, q2);
            d2min0 = fminf(d2min0, q0);
            d2min1 = fminf(d2min1, q1);
        }
    }

    // parity loop: tiny straddle list
    unsigned crossbits = 0;
    for (int v = 0; v < cntp; v += 2) {
#pragma unroll
        for (int u = 0; u < 2; u++) {
            float4 q = s_pp[v + u];     // {ay, by, slope, ax}
            float pay  = pyf - q.x;
            bool  cond = (q.x > pyf) != (q.y > pyf);
            float xint = fmaf(pay, q.z, q.w);
            int   kk   = (int)ceilf(xint - xbf);
            kk = min(max(kk, 0), PPT);
            unsigned m = (1u << kk) - 1u;
            crossbits ^= cond ? m : 0u;
        }
    }

    // ---- sigmoid + target bilinear + dice partials ----
    const float* __restrict__ mask = masks + (size_t)n * IMG * IMG;
    float ys = ub1 + (ub3 - ub1) * ((pyf + 0.5f) * (1.0f/(float)RES)) - 0.5f;
    float y0 = floorf(ys);
    float wy = ys - y0;
    int y0i = min(max((int)y0, 0), IMG-1);
    int y1i = min(y0i + 1, IMG-1);
    const float* r0p = mask + y0i*IMG;
    const float* r1p = mask + y1i*IMG;

    float inter = 0.0f, sp = 0.0f, st = 0.0f;
#pragma unroll
    for (int k = 0; k < PPT; k++) {
        float dmin = (k == 0) ? d2min0 : d2min1;
        float sign = (crossbits >> k) & 1u ? 1.0f : -1.0f;
        float xarg = sign * dmin * INV_S;
        float pred = 1.0f / (1.0f + __expf(-xarg));
        pred = fminf(fmaxf(pred, 1e-5f), 0.99999f);

        float xs = ub0 + (ub2 - ub0) * ((xbf + (float)k + 0.5f) * (1.0f/(float)RES)) - 0.5f;
        float x0 = floorf(xs);
        float wx = xs - x0;
        int x0i = min(max((int)x0, 0), IMG-1);
        int x1i = min(x0i + 1, IMG-1);
        float m00 = r0p[x0i], m01 = r0p[x1i];
        float m10 = r1p[x0i], m11 = r1p[x1i];
        float val = (1.0f - wy) * ((1.0f - wx)*m00 + wx*m01)
                  +          wy * ((1.0f - wx)*m10 + wx*m11);
        float tgt = (val >= 0.5f) ? 1.0f : 0.0f;

        inter += pred * tgt;
        sp    += pred;
        st    += tgt;
    }

    // ---- deterministic block reduce ----
#pragma unroll
    for (int o = 16; o > 0; o >>= 1) {
        inter += __shfl_down_sync(0xffffffffu, inter, o);
        sp    += __shfl_down_sync(0xffffffffu, sp,    o);
        st    += __shfl_down_sync(0xffffffffu, st,    o);
    }
    __shared__ float r_i[4], r_p[4], r_t[4];
    if (lid == 0) { r_i[wid] = inter; r_p[wid] = sp; r_t[wid] = st; }
    __syncthreads();
    if (tid == 0) {
        float ti = r_i[0]+r_i[1]+r_i[2]+r_i[3];
        float tp = r_p[0]+r_p[1]+r_p[2]+r_p[3];
        float tt = r_t[0]+r_t[1]+r_t[2]+r_t[3];
        g_part[b*3+0] = ti;
        g_part[b*3+1] = tp;
        g_part[b*3+2] = tt;
        __threadfence();
        int old = atomicAdd(&g_count, 1);
        s_last = (old == NBLOCKS - 1) ? 1 : 0;
    }
    __syncthreads();

    // ---- last block finalizes: per-instance dice + mean ----
    if (s_last) {
        float fi = 0.0f, fp = 0.0f, ft = 0.0f;   // instance = tid
#pragma unroll
        for (int c = 0; c < SPLIT; c++) {
            int slot = ((tid << 4) + c) * 3;
            fi += __ldcg(&g_part[slot+0]);
            fp += __ldcg(&g_part[slot+1]);
            ft += __ldcg(&g_part[slot+2]);
        }
        float loss = 1.0f - (2.0f*fi + 1.0f) / (fp + ft + 1.0f);
        s_vx[tid] = loss;                        // reuse smem as scratch
        __syncthreads();
        for (int o = THREADS/2; o > 0; o >>= 1) {
            if (tid < o) s_vx[tid] += s_vx[tid + o];
            __syncthreads();
        }
        if (tid == 0) {
            out[0] = s_vx[0] * (1.0f / (float)N_INST);
            g_count = 0;                          // reset for next graph replay
        }
    }
}

extern "C" void kernel_launch(void* const* d_in, const int* in_sizes, int n_in,
                              void* d_out, int out_size) {
    const float* preds  = (const float*)d_in[0];
    const float* masks  = (const float*)d_in[1];
    const float* bboxes = (const float*)d_in[2];
    float* out = (float*)d_out;

    fused_kernel<<<NBLOCKS, THREADS>>>(preds, masks, bboxes, out);
}